// round 17
// baseline (speedup 1.0000x reference)
#include <cuda_runtime.h>
#include <cuda_fp16.h>
#include <cstdint>

// ---------------- problem constants ----------------
#define HEADS_N 4
#define BSZ 2
#define NTOT 8192        // THW
#define MTOT 1024        // HW
#define CVTOT 512
#define M_T 32           // m-tile per block
#define NSPLIT 8
#define NPS (NTOT / NSPLIT)     // 1024
#define NCH 128                 // n per chunk
#define NCHUNKS (NPS / NCH)     // 8
#define NTHREADS 256
#define PSTRH 144               // P row stride in halves (72 words == 8 mod 32)
#define QSTR 80                 // Q row stride in halves (40 words == 8 mod 32)
#define PBUF (4 * 32 * PSTRH)   // 18432 halves (single P buffer)

// ---------------- device scratch (no cudaMalloc allowed) ----------------
__device__ __align__(16) float g_partial[NSPLIT * BSZ * CVTOT * MTOT]; // 32 MB
// Kt fp16 fragment-native (m16n8k16 A): [b][h][ngrp(512)][kstep(2)][lane(32)][8]  (4 MB)
__device__ __align__(16) __half g_kth[BSZ * HEADS_N * 512 * 2 * 256];
// Q fp16: [b][h][m][32 halves, fragment-ordered]  (0.5 MB)
__device__ __align__(16) __half g_Qh[BSZ * HEADS_N * MTOT * 32];
__device__ __align__(16) float g_bias[BSZ * HEADS_N * MTOT];           // 32 KB
// mv fp16 fragment-native for m16n8k16: [b][B16(32)][ngrp(512)][lane(32)][8] (16.7 MB)
__device__ __align__(16) __half g_mvph[BSZ * CVTOT * NTOT];

// ---------------- smem layout (float offsets) ----------------
#define F_BIAS 0                          // bias[4][32] fp32
#define F_MS   128                        // ms[1024] fp32
#define F_QH   (F_MS + NPS)               // 1152 : Q fp16 [4][32][QSTR]
#define F_PH   (F_QH + 4 * 32 * QSTR / 2) // 3712 : P fp16, single buffer
#define F_MVH  (F_PH + PBUF / 2)          // 12928 : mv stage, 8 warps x 2 bufs x 1024 halves
#define SM_TOTAL ((F_MVH + 8192) * 4)     // 84480 B -> 2 CTAs = 168960 <= 227KB ✓

// ---------------- helpers ----------------
__device__ __forceinline__ float ex2f(float x) {
    float y;
    asm("ex2.approx.f32 %0, %1;" : "=f"(y) : "f"(x));
    return y;
}
__device__ __forceinline__ uint32_t pack_h2(float lo, float hi) {
    uint32_t r;
    asm("cvt.rn.f16x2.f32 %0, %1, %2;" : "=r"(r) : "f"(hi), "f"(lo));
    return r;
}
__device__ __forceinline__ void mma_f16(float* d, uint4 a, uint2 b) {
    asm volatile(
        "mma.sync.aligned.m16n8k16.row.col.f32.f16.f16.f32 "
        "{%0,%1,%2,%3},{%4,%5,%6,%7},{%8,%9},{%0,%1,%2,%3};"
        : "+f"(d[0]), "+f"(d[1]), "+f"(d[2]), "+f"(d[3])
        : "r"(a.x), "r"(a.y), "r"(a.z), "r"(a.w), "r"(b.x), "r"(b.y));
}
__device__ __forceinline__ uint32_t smem_u32(const void* p) {
    uint32_t a;
    asm("{ .reg .u64 t; cvta.to.shared.u64 t, %1; cvt.u32.u64 %0, t; }"
        : "=r"(a) : "l"(p));
    return a;
}
#define CP_ASYNC16(dst, src) \
    asm volatile("cp.async.cg.shared.global [%0], [%1], 16;" :: "r"(dst), "l"(src))
#define CP_COMMIT() asm volatile("cp.async.commit_group;" ::: "memory")
#define CP_WAIT1()  asm volatile("cp.async.wait_group 1;" ::: "memory")
#define CP_WAIT0()  asm volatile("cp.async.wait_group 0;" ::: "memory")

// ---------------- precompute kernels ----------------
__global__ void prep_kth(const float* __restrict__ mk) {
    int i = blockIdx.x * blockDim.x + threadIdx.x;      // over BSZ*64*NTOT
    if (i >= BSZ * 64 * NTOT) return;
    int n  = i & (NTOT - 1);
    int ck = (i >> 13) & 63;
    int b  = i >> 19;
    float v = mk[i];
    int h = ck >> 4, c = ck & 15;
    int ngrp = n >> 4, nn = n & 15, g = nn & 7, hf = nn >> 3;
    int t = (c & 7) >> 1, d = c & 1, s = c >> 3;
    int hp = s * 4 + hf * 2 + d;
    size_t base = ((((size_t)(b * HEADS_N + h) * 512 + ngrp) * 2) * 32
                   + (g * 4 + t)) * 8 + hp;
    g_kth[base]       = __float2half_rn(v * v * v);   // kstep 0
    g_kth[base + 256] = __float2half_rn(v);           // kstep 1
}

__device__ __forceinline__ int pos16(int kk) {
    return 4 * ((kk & 7) >> 1) + 2 * (kk >> 3) + (kk & 1);
}

__global__ void prep_q(const float* __restrict__ qk, const float* __restrict__ qe) {
    int i = blockIdx.x * blockDim.x + threadIdx.x;      // over BSZ*4*MTOT
    if (i >= BSZ * HEADS_N * MTOT) return;
    int m = i & (MTOT - 1);
    int h = (i >> 10) & 3;
    int b = i >> 12;
    size_t qb = (size_t)i * 32;
    float bias = 0.0f;
    #pragma unroll
    for (int c = 0; c < 16; c++) {
        size_t gi = ((size_t)(b * 64 + h * 16 + c)) * MTOT + m;
        float e = qe[gi];
        float k = qk[gi];
        int p = pos16(c);
        g_Qh[qb + p]      = __float2half_rn(-e);
        g_Qh[qb + 16 + p] = __float2half_rn(2.0f * k * e);
        bias += e * k * k * k;
    }
    g_bias[i] = bias;
}

__global__ void prep_mv(const float* __restrict__ mv) {
    int f = blockIdx.x * blockDim.x + threadIdx.x;
    if (f >= BSZ * CVTOT * NTOT / 8) return;
    int t    = f & 3;
    int g    = (f >> 2) & 7;
    int ngrp = (f >> 5) & 511;
    int B16  = (f >> 14) & 31;
    int b    = f >> 19;
    const float* r0 = mv + (((size_t)(b * CVTOT + B16 * 16 + g)) << 13) + ngrp * 16;
    const float* r1 = r0 + ((size_t)8 << 13);
    __half2 x = __floats2half2_rn(r0[t],     r0[t + 8]);
    __half2 y = __floats2half2_rn(r1[t],     r1[t + 8]);
    __half2 z = __floats2half2_rn(r0[t + 4], r0[t + 12]);
    __half2 w = __floats2half2_rn(r1[t + 4], r1[t + 12]);
    uint4 v = { *(uint32_t*)&x, *(uint32_t*)&y, *(uint32_t*)&z, *(uint32_t*)&w };
    *(uint4*)((char*)g_mvph + (size_t)f * 16) = v;
}

// ---------------- main fused kernel ----------------
__global__ void __launch_bounds__(NTHREADS, 2)
mr_main(const float* __restrict__ ms)
{
    extern __shared__ float sm[];
    __half* smQ = (__half*)(sm + F_QH);
    __half* smP = (__half*)(sm + F_PH);
    const int tid  = threadIdx.x;
    const int w    = tid >> 5;       // 0..7
    const int lane = tid & 31;
    const int gid  = lane >> 2;      // 0..7
    const int tig  = lane & 3;       // 0..3

    // warp-private mv staging: 2 buffers x 1024 halves
    __half* smV = (__half*)(sm + F_MVH) + w * 2048;
    const uint32_t svb = smem_u32(smV) + lane * 16;

    const int bx    = blockIdx.x;    // 512 blocks
    const int split = bx & 7;
    const int mtile = (bx >> 3) & 31;
    const int b     = bx >> 8;
    const int m0    = mtile * M_T;
    const int nbase = split * NPS;

    // ---- stage bias + ms (whole split) + Q fp16 (block-constant) ----
    if (tid < 128)
        sm[F_BIAS + tid] = g_bias[(size_t)(b * HEADS_N + (tid >> 5)) * MTOT + m0 + (tid & 31)];
    #pragma unroll
    for (int it = 0; it < NPS / NTHREADS; it++) {
        int i = tid + it * NTHREADS;
        sm[F_MS + i] = ms[(size_t)b * NTOT + nbase + i];
    }
    {
        const uint4* qsrc = (const uint4*)(g_Qh + ((size_t)(b * HEADS_N) * MTOT) * 32);
        #pragma unroll
        for (int it = 0; it < 2; it++) {
            int j = tid + it * NTHREADS;         // 512 uint4
            int q = j & 3, mm = (j >> 2) & 31, h = j >> 7;
            uint4 v = qsrc[((size_t)h * MTOT + m0 + mm) * 4 + q];
            *(uint4*)(smQ + (h * 32 + mm) * QSTR + ((mm >> 2) & 1) * 16 + q * 8) = v;
        }
    }

    // Phase A mapping: warp = (ntile 0..3, mtile2 0..1), all 4 heads in-register
    const int nt  = w & 3;
    const int mA0 = (w >> 2) * 16;
    // Phase B mapping: one head per 2 warps, 64cv x 32m per warp
    const int headB = w >> 1;
    const int cvq   = w & 1;

    float acc[4][4][4];   // O accumulators [cvblk16][mt][reg]
    #pragma unroll
    for (int rt = 0; rt < 4; rt++)
        #pragma unroll
        for (int mt = 0; mt < 4; mt++)
            #pragma unroll
            for (int r = 0; r < 4; r++) acc[rt][mt][r] = 0.0f;

    // fragment-native bases
    const __half* gmb = g_mvph +
        ((size_t)(b * 32 + headB * 8 + cvq * 4) * 512) * 256 + lane * 8;
    const __half* kthb = g_kth + (size_t)(b * HEADS_N) * 512 * 2 * 256;
    const __half* pbh = smP + headB * (32 * PSTRH);
    const int prd = ((gid >> 2) & 1) * 16;
    const int qsh = ((gid >> 2) & 1) * 16;

    const float SC = 0.18033688f;   // 0.125 * log2(e)

    __syncthreads();

    for (int chunk = 0; chunk < NCHUNKS; chunk++) {
        const int n0 = nbase + chunk * NCH;

        // ---- prefetch mv g16 = 0,1 via cp.async (hidden under Phase A) ----
        #pragma unroll
        for (int pf = 0; pf < 2; pf++) {
            const size_t ngrp = (size_t)(n0 >> 4) + pf;
            uint32_t dst = svb + pf * 2048;            // buffer pf
            #pragma unroll
            for (int blk = 0; blk < 4; blk++)
                CP_ASYNC16(dst + blk * 512,
                           gmb + ((size_t)blk * 512 + ngrp) * 256);
            CP_COMMIT();
        }

        // ===== Phase A (fp16 m16n8k16): two 64-n sub-passes =====
        #pragma unroll
        for (int p = 0; p < 2; p++) {
            float sacc[4][2][4];
            #pragma unroll
            for (int h = 0; h < 4; h++)
                #pragma unroll
                for (int j = 0; j < 2; j++)
                    #pragma unroll
                    for (int r = 0; r < 4; r++) sacc[h][j][r] = 0.0f;

            const int ngrp = (n0 >> 4) + p * 4 + nt;
            #pragma unroll
            for (int ks = 0; ks < 2; ks++) {
                #pragma unroll
                for (int h = 0; h < 4; h++) {
                    uint4 aA = *(const uint4*)(kthb +
                        (((size_t)h * 512 + ngrp) * 2 + ks) * 256 + lane * 8);
                    #pragma unroll
                    for (int j = 0; j < 2; j++) {
                        uint2 bq = *(const uint2*)(smQ +
                            (h * 32 + mA0 + j * 8 + gid) * QSTR + ks * 16 + tig * 4 + qsh);
                        mma_f16(sacc[h][j], aA, bq);
                    }
                }
            }

            // ---- softmax over heads (log2 domain), pack fp16 pairs, store P ----
            {
                const int nAl = p * 64 + nt * 16 + gid;
                const float msa = sm[F_MS + chunk * NCH + nAl] * SC;
                const float msb = sm[F_MS + chunk * NCH + nAl + 8] * SC;
                const int grp = p * 4 + nt;
                const int woff = grp * 16 + (gid & 3) * 4 + (gid >> 2) * 2;
                #pragma unroll
                for (int j = 0; j < 2; j++) {
                    #pragma unroll
                    for (int c = 0; c < 2; c++) {
                        int m = mA0 + j * 8 + 2 * tig + c;
                        float b0 = sm[F_BIAS + m];
                        float b1 = sm[F_BIAS + 32 + m];
                        float b2 = sm[F_BIAS + 64 + m];
                        float b3 = sm[F_BIAS + 96 + m];
                        float ea0 = ex2f((sacc[0][j][c] - b0) * msa);
                        float ea1 = ex2f((sacc[1][j][c] - b1) * msa);
                        float ea2 = ex2f((sacc[2][j][c] - b2) * msa);
                        float ea3 = ex2f((sacc[3][j][c] - b3) * msa);
                        float inva = __fdividef(1.0f, ea0 + ea1 + ea2 + ea3 + 1e-30f);
                        float eb0 = ex2f((sacc[0][j][2 + c] - b0) * msb);
                        float eb1 = ex2f((sacc[1][j][2 + c] - b1) * msb);
                        float eb2 = ex2f((sacc[2][j][2 + c] - b2) * msb);
                        float eb3 = ex2f((sacc[3][j][2 + c] - b3) * msb);
                        float invb = __fdividef(1.0f, eb0 + eb1 + eb2 + eb3 + 1e-30f);
                        uint32_t pk0  = pack_h2(ea0 * inva, eb0 * invb);
                        uint32_t pk1  = pack_h2(ea1 * inva, eb1 * invb);
                        uint32_t pk2v = pack_h2(ea2 * inva, eb2 * invb);
                        uint32_t pk3  = pack_h2(ea3 * inva, eb3 * invb);
                        int roff = m * PSTRH + woff + ((m >> 2) & 1) * 16;
                        *(uint32_t*)(smP + roff)              = pk0;
                        *(uint32_t*)(smP + 32 * PSTRH + roff) = pk1;
                        *(uint32_t*)(smP + 64 * PSTRH + roff) = pk2v;
                        *(uint32_t*)(smP + 96 * PSTRH + roff) = pk3;
                    }
                }
            }
        }
        __syncthreads();

        // ===== Phase B (fp16 m16n8k16) with cp.async depth-2 pipeline =====
        #pragma unroll
        for (int g16 = 0; g16 < 8; g16++) {
            // data for g16 was committed in group g16; keep exactly the groups
            // newer than it pending. Final iteration: its group IS the newest.
            if (g16 == 7) { CP_WAIT0(); } else { CP_WAIT1(); }
            const __half* pv = smV + (g16 & 1) * 1024 + lane * 8;
            uint4 av0 = *(const uint4*)(pv);
            uint4 av1 = *(const uint4*)(pv + 256);
            uint4 av2 = *(const uint4*)(pv + 512);
            uint4 av3 = *(const uint4*)(pv + 768);
            #pragma unroll
            for (int mt = 0; mt < 4; mt++) {
                uint2 bb = *(const uint2*)(pbh + (mt * 8 + gid) * PSTRH + g16 * 16
                                           + tig * 4 + prd);
                mma_f16(acc[0][mt], av0, bb);
                mma_f16(acc[1][mt], av1, bb);
                mma_f16(acc[2][mt], av2, bb);
                mma_f16(acc[3][mt], av3, bb);
            }
            if (g16 < 6) {
                const size_t ngrp2 = (size_t)(n0 >> 4) + g16 + 2;
                uint32_t dst = svb + (g16 & 1) * 2048;
                #pragma unroll
                for (int blk = 0; blk < 4; blk++)
                    CP_ASYNC16(dst + blk * 512,
                               gmb + ((size_t)blk * 512 + ngrp2) * 256);
                CP_COMMIT();
            }
        }
        __syncthreads();   // P buffer reused next chunk
    }

    // ---- writeout: fragment-direct STG.64 into g_partial ----
    {
        const int cv0 = headB * 128 + cvq * 64;
        float* pp = g_partial +
            ((size_t)(split * BSZ + b) * CVTOT + cv0) * MTOT + m0;
        #pragma unroll
        for (int blk = 0; blk < 4; blk++) {
            #pragma unroll
            for (int mt = 0; mt < 4; mt++) {
                int m = mt * 8 + 2 * tig;
                float2 lo = { acc[blk][mt][0], acc[blk][mt][1] };
                float2 hi = { acc[blk][mt][2], acc[blk][mt][3] };
                *(float2*)(pp + (size_t)(blk * 16 + gid) * MTOT + m)     = lo;
                *(float2*)(pp + (size_t)(blk * 16 + gid + 8) * MTOT + m) = hi;
            }
        }
    }
}

// ---------------- assemble: reduce 8 splits + copy qv ----------------
__global__ void assemble_kernel(const float* __restrict__ qv, float* __restrict__ out)
{
    const int total4 = BSZ * 2 * CVTOT * MTOT / 4;
    int idx = blockIdx.x * blockDim.x + threadIdx.x;
    if (idx >= total4) return;
    int gf  = idx * 4;
    int b   = gf >> 20;
    int rem = gf & ((1 << 20) - 1);
    int ch  = rem >> 10;
    int m   = rem & 1023;

    float4 r;
    if (ch < CVTOT) {
        const size_t stride = (size_t)BSZ * CVTOT * MTOT;
        size_t off = ((size_t)b * CVTOT + ch) * MTOT + m;
        r = make_float4(0.f, 0.f, 0.f, 0.f);
        #pragma unroll
        for (int s = 0; s < NSPLIT; s++) {
            float4 a = *reinterpret_cast<const float4*>(g_partial + s * stride + off);
            r.x += a.x; r.y += a.y; r.z += a.z; r.w += a.w;
        }
    } else {
        r = *reinterpret_cast<const float4*>(
                qv + ((size_t)b * CVTOT + (ch - CVTOT)) * MTOT + m);
    }
    *reinterpret_cast<float4*>(out + (size_t)gf) = r;
}

extern "C" void kernel_launch(void* const* d_in, const int* in_sizes, int n_in,
                              void* d_out, int out_size)
{
    const float* mk = (const float*)d_in[0];
    const float* qk = (const float*)d_in[1];
    const float* ms = (const float*)d_in[2];
    const float* qe = (const float*)d_in[3];
    const float* mv = (const float*)d_in[4];
    const float* qv = (const float*)d_in[5];
    float* out = (float*)d_out;

    prep_kth<<<(BSZ * 64 * NTOT + 255) / 256, 256>>>(mk);
    prep_q<<<(BSZ * HEADS_N * MTOT + 255) / 256, 256>>>(qk, qe);
    prep_mv<<<(BSZ * CVTOT * NTOT / 8 + 255) / 256, 256>>>(mv);

    cudaFuncSetAttribute(mr_main, cudaFuncAttributeMaxDynamicSharedMemorySize,
                         SM_TOTAL);
    mr_main<<<BSZ * (MTOT / M_T) * NSPLIT, NTHREADS, SM_TOTAL>>>(ms);

    const int total4 = BSZ * 2 * CVTOT * MTOT / 4;
    assemble_kernel<<<(total4 + 255) / 256, 256>>>(qv, out);
}